// round 1
// baseline (speedup 1.0000x reference)
#include <cuda_runtime.h>

// SimplifiedTopologyExtractor — algebraic reduction:
// pooled == embeddings (the gather indexes a constant dimension), so
// out = ReLU(LayerNorm(emb[:, :, :256] @ W_enc + b_enc)).
// Single fused GEMM (M=16384,N=512,K=256) + row LayerNorm + ReLU.
// fp32 math via packed fma.rn.f32x2 (FFMA2) for full-rate FP32 on sm_103a.

#define BM 32
#define BK 16
#define NN 512
#define KD 256
#define NSTEP (KD / BK)
#define ASTRIDE 68   // padded float stride per k-row of duplicated-A tile
#define SMEM_FLOATS (2 * BK * ASTRIDE + 2 * BK * NN)
#define SMEM_BYTES (SMEM_FLOATS * 4)

__device__ __forceinline__ void cp_async16(unsigned int smem_addr, const void* gptr) {
    asm volatile("cp.async.cg.shared.global [%0], [%1], 16;\n"
                 :: "r"(smem_addr), "l"(gptr));
}

__global__ void __launch_bounds__(256, 2)
topo_fused_kernel(const float* __restrict__ emb,
                  const float* __restrict__ W,
                  const float* __restrict__ bias,
                  const float* __restrict__ gamma,
                  const float* __restrict__ beta,
                  float* __restrict__ out)
{
    extern __shared__ float smem[];
    float* As = smem;                     // [2][BK][ASTRIDE]  (duplicated pairs {a,a})
    float* Bs = smem + 2 * BK * ASTRIDE;  // [2][BK][NN]

    const int tid   = threadIdx.x;
    const int m0    = blockIdx.x * BM;
    const int col_t = tid & 63;   // 64 column-threads
    const int row_t = tid >> 6;   // 4 row-threads
    const int c0    = col_t * 4;  // thread cols: [c0..c0+3] and [256+c0..256+c0+3]
    const int r0    = row_t * 8;  // thread rows: r0..r0+7

    // accumulators: 8 rows x 4 col-pairs, packed f32x2 in u64
    unsigned long long acc[8][4];
    #pragma unroll
    for (int r = 0; r < 8; r++)
        #pragma unroll
        for (int p = 0; p < 4; p++) acc[r][p] = 0ull;

    float a_pre[2];

    // ---- prologue: tile 0 ----
    {
        unsigned int bdst = (unsigned int)__cvta_generic_to_shared(Bs);
        const float4* src = (const float4*)W;   // tile t = contiguous W + t*BK*NN
        #pragma unroll
        for (int i = 0; i < 8; i++)
            cp_async16(bdst + (unsigned)(tid + i * 256) * 16, src + tid + i * 256);
        asm volatile("cp.async.commit_group;\n");
        #pragma unroll
        for (int i = 0; i < 2; i++) {
            int e = tid + i * 256;          // e in [0,512): m = e>>4, kk = e&15
            float v = emb[(m0 + (e >> 4)) * 512 + (e & 15)];
            *(float2*)(As + (e & 15) * ASTRIDE + 2 * (e >> 4)) = make_float2(v, v);
        }
    }

    for (int t = 0; t < NSTEP; t++) {
        const int cur = t & 1;
        const int nxt = cur ^ 1;
        if (t + 1 < NSTEP) {
            unsigned int bdst =
                (unsigned int)__cvta_generic_to_shared(Bs + nxt * (BK * NN));
            const float4* src = (const float4*)(W + (t + 1) * BK * NN);
            #pragma unroll
            for (int i = 0; i < 8; i++)
                cp_async16(bdst + (unsigned)(tid + i * 256) * 16, src + tid + i * 256);
            asm volatile("cp.async.commit_group;\n");
            #pragma unroll
            for (int i = 0; i < 2; i++) {
                int e = tid + i * 256;
                a_pre[i] = emb[(m0 + (e >> 4)) * 512 + (t + 1) * BK + (e & 15)];
            }
            asm volatile("cp.async.wait_group 1;\n");
        } else {
            asm volatile("cp.async.wait_group 0;\n");
        }
        __syncthreads();   // tile `cur` fully visible to all threads

        const float* Ac = As + cur * (BK * ASTRIDE);
        const float* Bc = Bs + cur * (BK * NN);
        #pragma unroll
        for (int kk = 0; kk < BK; kk++) {
            const ulonglong2* ap = (const ulonglong2*)(Ac + kk * ASTRIDE + 2 * r0);
            ulonglong2 a01 = ap[0];
            ulonglong2 a23 = ap[1];
            ulonglong2 a45 = ap[2];
            ulonglong2 a67 = ap[3];
            ulonglong2 b01 = *(const ulonglong2*)(Bc + kk * NN + c0);
            ulonglong2 b23 = *(const ulonglong2*)(Bc + kk * NN + 256 + c0);
            unsigned long long av[8] = {a01.x, a01.y, a23.x, a23.y,
                                        a45.x, a45.y, a67.x, a67.y};
            unsigned long long bv[4] = {b01.x, b01.y, b23.x, b23.y};
            #pragma unroll
            for (int r = 0; r < 8; r++)
                #pragma unroll
                for (int p = 0; p < 4; p++)
                    asm("fma.rn.f32x2 %0, %1, %2, %0;"
                        : "+l"(acc[r][p]) : "l"(av[r]), "l"(bv[p]));
        }
        __syncthreads();   // all readers done with `cur` before it is refilled

        if (t + 1 < NSTEP) {
            float* Ad = As + nxt * (BK * ASTRIDE);
            #pragma unroll
            for (int i = 0; i < 2; i++) {
                int e = tid + i * 256;
                *(float2*)(Ad + (e & 15) * ASTRIDE + 2 * (e >> 4)) =
                    make_float2(a_pre[i], a_pre[i]);
            }
        }
    }

    // ---- fused epilogue: + bias, LayerNorm over N=512, * gamma + beta, ReLU ----
    float2 hv[8][4];
    {
        const float4 bA = *(const float4*)(bias + c0);
        const float4 bB = *(const float4*)(bias + 256 + c0);
        float2 badd[4] = { {bA.x, bA.y}, {bA.z, bA.w}, {bB.x, bB.y}, {bB.z, bB.w} };
        #pragma unroll
        for (int r = 0; r < 8; r++)
            #pragma unroll
            for (int p = 0; p < 4; p++) {
                union { unsigned long long u; float2 f; } cvt;
                cvt.u = acc[r][p];
                float2 v = cvt.f;
                v.x += badd[p].x;
                v.y += badd[p].y;
                hv[r][p] = v;
            }
    }

    // smem reuse (all GEMM reads are behind the last __syncthreads above)
    float*  rsum = smem;                    // [32][64]
    float*  rsq  = smem + 2048;             // [32][64]
    float2* mstd = (float2*)(smem + 4096);  // [32] {mu, rstd}

    #pragma unroll
    for (int r = 0; r < 8; r++) {
        float s = 0.f, q = 0.f;
        #pragma unroll
        for (int p = 0; p < 4; p++) {
            float2 v = hv[r][p];
            s += v.x + v.y;
            q += v.x * v.x + v.y * v.y;
        }
        rsum[(r0 + r) * 64 + col_t] = s;
        rsq [(r0 + r) * 64 + col_t] = q;
    }
    __syncthreads();

    {
        const int row = tid >> 3;   // 0..31
        const int seg = tid & 7;    // 8 threads per row
        float s = 0.f, q = 0.f;
        #pragma unroll
        for (int i = 0; i < 8; i++) {
            s += rsum[row * 64 + seg * 8 + i];
            q += rsq [row * 64 + seg * 8 + i];
        }
        s += __shfl_xor_sync(0xffffffffu, s, 1);
        q += __shfl_xor_sync(0xffffffffu, q, 1);
        s += __shfl_xor_sync(0xffffffffu, s, 2);
        q += __shfl_xor_sync(0xffffffffu, q, 2);
        s += __shfl_xor_sync(0xffffffffu, s, 4);
        q += __shfl_xor_sync(0xffffffffu, q, 4);
        if (seg == 0) {
            float mu  = s * (1.0f / 512.0f);
            float var = q * (1.0f / 512.0f) - mu * mu;
            mstd[row] = make_float2(mu, rsqrtf(var + 1e-5f));
        }
    }
    __syncthreads();

    const float4 gA = *(const float4*)(gamma + c0);
    const float4 gB = *(const float4*)(gamma + 256 + c0);
    const float4 tA = *(const float4*)(beta + c0);
    const float4 tB = *(const float4*)(beta + 256 + c0);
    float g [8] = {gA.x, gA.y, gA.z, gA.w, gB.x, gB.y, gB.z, gB.w};
    float bt[8] = {tA.x, tA.y, tA.z, tA.w, tB.x, tB.y, tB.z, tB.w};

    #pragma unroll
    for (int r = 0; r < 8; r++) {
        float2 ms = mstd[r0 + r];
        float o[8];
        #pragma unroll
        for (int p = 0; p < 4; p++) {
            float2 v = hv[r][p];
            o[2 * p]     = (v.x - ms.x) * ms.y;
            o[2 * p + 1] = (v.y - ms.x) * ms.y;
        }
        #pragma unroll
        for (int j = 0; j < 8; j++)
            o[j] = fmaxf(o[j] * g[j] + bt[j], 0.0f);
        const long rowg = (long)(m0 + r0 + r);
        *(float4*)(out + rowg * 512 + c0)       = make_float4(o[0], o[1], o[2], o[3]);
        *(float4*)(out + rowg * 512 + 256 + c0) = make_float4(o[4], o[5], o[6], o[7]);
    }
}

extern "C" void kernel_launch(void* const* d_in, const int* in_sizes, int n_in,
                              void* d_out, int out_size)
{
    // metadata order: embeddings, W_proj, b_proj, W_enc, b_enc, ln_gamma, ln_beta
    const float* emb   = (const float*)d_in[0];
    const float* W_enc = (const float*)d_in[3];
    const float* b_enc = (const float*)d_in[4];
    const float* gam   = (const float*)d_in[5];
    const float* bet   = (const float*)d_in[6];
    float* out = (float*)d_out;

    cudaFuncSetAttribute(topo_fused_kernel,
                         cudaFuncAttributeMaxDynamicSharedMemorySize, SMEM_BYTES);
    topo_fused_kernel<<<16384 / BM, 256, SMEM_BYTES>>>(emb, W_enc, b_enc, gam, bet, out);
}

// round 3
// speedup vs baseline: 1.8680x; 1.8680x over previous
#include <cuda_runtime.h>
#include <cuda_bf16.h>
#include <cstdint>

// ============================================================================
// SimplifiedTopologyExtractor — algebraic reduction:
//   out = ReLU(LayerNorm(emb[:, :, :256] @ W_enc + b_enc))
// (pooled == embeddings exactly; proj/cdist/topk is dead code.)
//
// fp32 GEMM via bf16 hi/lo split on the legacy tensor path (mma.sync m16n8k16,
// base-sm_103-compatible; tcgen05 requires sm_103a PTX target which this
// harness does not emit):   a*b ≈ ah*bh + ah*bl + al*bh  (err ~2^-18 rel).
// Single fused kernel: CTA owns full N=512 row -> LayerNorm+ReLU in-register.
// ============================================================================

#define THREADS 256
#define MTILE 64
#define NN 512
#define KD 256
#define KCH 16
#define NCHUNK (KD / KCH)

// smem strides/offsets (bytes)
#define A_STRIDE 48            // 16 bf16 (32B) + 16B pad -> conflict-free LDSM
#define B_STRIDE 1040          // 512 bf16 (1024B) + 16B pad
#define OFF_AH 0
#define OFF_AL (64 * A_STRIDE)                  // 3072
#define OFF_BH (2 * 64 * A_STRIDE)              // 6144
#define OFF_BL (OFF_BH + KCH * B_STRIDE)        // 22784
#define STAGE  (OFF_BL + KCH * B_STRIDE)        // 39424
#define OFF_PS (2 * STAGE)                      // 78848
#define OFF_PQ (OFF_PS + 2048)
#define OFF_MZ (OFF_PQ + 2048)
#define SMEM_TOTAL (OFF_MZ + 512)               // 83456

__device__ __forceinline__ uint32_t smem_u32(const void* p) {
    uint32_t a;
    asm("{ .reg .u64 t; cvta.to.shared.u64 t, %1; cvt.u32.u64 %0, t; }"
        : "=r"(a) : "l"(p));
    return a;
}

__device__ __forceinline__ void ldsm4(uint32_t* r, uint32_t addr) {
    asm volatile("ldmatrix.sync.aligned.m8n8.x4.shared.b16 {%0,%1,%2,%3}, [%4];"
                 : "=r"(r[0]), "=r"(r[1]), "=r"(r[2]), "=r"(r[3]) : "r"(addr));
}
__device__ __forceinline__ void ldsm4t(uint32_t* r, uint32_t addr) {
    asm volatile("ldmatrix.sync.aligned.m8n8.x4.trans.shared.b16 {%0,%1,%2,%3}, [%4];"
                 : "=r"(r[0]), "=r"(r[1]), "=r"(r[2]), "=r"(r[3]) : "r"(addr));
}

__device__ __forceinline__ void mma16816(float* d, const uint32_t* a,
                                         uint32_t b0, uint32_t b1) {
    asm volatile(
        "mma.sync.aligned.m16n8k16.row.col.f32.bf16.bf16.f32 "
        "{%0,%1,%2,%3}, {%4,%5,%6,%7}, {%8,%9}, {%0,%1,%2,%3};"
        : "+f"(d[0]), "+f"(d[1]), "+f"(d[2]), "+f"(d[3])
        : "r"(a[0]), "r"(a[1]), "r"(a[2]), "r"(a[3]), "r"(b0), "r"(b1));
}

// split float4 -> hi/lo bf16x2 pairs (elements n,n+1 packed lo/hi 16 bits)
__device__ __forceinline__ void split_f4(float4 v, uint32_t& h01, uint32_t& h23,
                                         uint32_t& l01, uint32_t& l23) {
    float f[4] = {v.x, v.y, v.z, v.w};
    unsigned short hs[4], ls[4];
#pragma unroll
    for (int i = 0; i < 4; i++) {
        __nv_bfloat16 h = __float2bfloat16(f[i]);
        float rem = f[i] - __bfloat162float(h);
        __nv_bfloat16 l = __float2bfloat16(rem);
        hs[i] = __bfloat16_as_ushort(h);
        ls[i] = __bfloat16_as_ushort(l);
    }
    h01 = (uint32_t)hs[0] | ((uint32_t)hs[1] << 16);
    h23 = (uint32_t)hs[2] | ((uint32_t)hs[3] << 16);
    l01 = (uint32_t)ls[0] | ((uint32_t)ls[1] << 16);
    l23 = (uint32_t)ls[2] | ((uint32_t)ls[3] << 16);
}

__global__ void __launch_bounds__(THREADS)
gemm_ln_kernel(const float* __restrict__ emb,
               const float* __restrict__ W,
               const float* __restrict__ bias,
               const float* __restrict__ gamma,
               const float* __restrict__ beta,
               float* __restrict__ out)
{
    extern __shared__ __align__(1024) unsigned char smem[];
    const uint32_t sb = smem_u32(smem);
    const int tid = threadIdx.x;
    const int wid = tid >> 5;
    const int lane = tid & 31;
    const int m0 = blockIdx.x * MTILE;

    float acc[4][8][4];
#pragma unroll
    for (int mt = 0; mt < 4; mt++)
#pragma unroll
        for (int nt = 0; nt < 8; nt++)
#pragma unroll
            for (int e = 0; e < 4; e++) acc[mt][nt][e] = 0.0f;

    // gmem staging mappings
    const int ar = tid >> 2, ac = tid & 3;     // A: 64 rows x 4 quads of k
    const int br = tid >> 4, bc = tid & 15;    // B: 16 rows x 16 col4 base
    float4 aS;
    float4 bS[8];

    // prologue: chunk 0
    aS = *(const float4*)(emb + (size_t)(m0 + ar) * 512 + ac * 4);
#pragma unroll
    for (int i = 0; i < 8; i++)
        bS[i] = *(const float4*)(W + (size_t)br * 512 + (bc + i * 16) * 4);

    // ldmatrix lane addressing
    const uint32_t lrow = lane & 15, lchk = lane >> 4;
    const uint32_t aLane = lrow * A_STRIDE + lchk * 16;
    const uint32_t bLane = lrow * B_STRIDE + lchk * 16 + (uint32_t)wid * 128;

#pragma unroll 1
    for (int c = 0; c < NCHUNK; ++c) {
        const uint32_t st = (c & 1) ? (uint32_t)STAGE : 0u;

        // ---- STS chunk c (convert in-register) ----
        {
            uint32_t h01, h23, l01, l23;
            split_f4(aS, h01, h23, l01, l23);
            *(uint2*)(smem + st + OFF_AH + ar * A_STRIDE + ac * 8) = make_uint2(h01, h23);
            *(uint2*)(smem + st + OFF_AL + ar * A_STRIDE + ac * 8) = make_uint2(l01, l23);
#pragma unroll
            for (int i = 0; i < 8; i++) {
                split_f4(bS[i], h01, h23, l01, l23);
                *(uint2*)(smem + st + OFF_BH + br * B_STRIDE + (bc + i * 16) * 8) =
                    make_uint2(h01, h23);
                *(uint2*)(smem + st + OFF_BL + br * B_STRIDE + (bc + i * 16) * 8) =
                    make_uint2(l01, l23);
            }
        }
        __syncthreads();

        // ---- prefetch chunk c+1 into registers (overlaps with MMA) ----
        if (c + 1 < NCHUNK) {
            const int k0 = (c + 1) * KCH;
            aS = *(const float4*)(emb + (size_t)(m0 + ar) * 512 + k0 + ac * 4);
#pragma unroll
            for (int i = 0; i < 8; i++)
                bS[i] = *(const float4*)(W + (size_t)(k0 + br) * 512 + (bc + i * 16) * 4);
        }

        // ---- MMA sweep on chunk c ----
        uint32_t Ah[4][4], Al[4][4];
#pragma unroll
        for (int mt = 0; mt < 4; mt++) {
            ldsm4(Ah[mt], sb + st + OFF_AH + (uint32_t)mt * 16 * A_STRIDE + aLane);
            ldsm4(Al[mt], sb + st + OFF_AL + (uint32_t)mt * 16 * A_STRIDE + aLane);
        }
#pragma unroll
        for (int j = 0; j < 4; j++) {
            uint32_t Bh[4], Bl[4];
            ldsm4t(Bh, sb + st + OFF_BH + (uint32_t)j * 32 + bLane);
            ldsm4t(Bl, sb + st + OFF_BL + (uint32_t)j * 32 + bLane);
#pragma unroll
            for (int mt = 0; mt < 4; mt++) {
#pragma unroll
                for (int nn = 0; nn < 2; nn++) {
                    float* d = acc[mt][j * 2 + nn];
                    mma16816(d, Ah[mt], Bh[nn * 2], Bh[nn * 2 + 1]);
                    mma16816(d, Ah[mt], Bl[nn * 2], Bl[nn * 2 + 1]);
                    mma16816(d, Al[mt], Bh[nn * 2], Bh[nn * 2 + 1]);
                }
            }
        }
    }

    // ======== fused epilogue: +bias, LayerNorm(512), *gamma+beta, ReLU ========
    const int g = lane >> 2, t4 = lane & 3;
    float* ps = (float*)(smem + OFF_PS);      // [64 rows][8 warps]
    float* pq = (float*)(smem + OFF_PQ);
    float2* mz = (float2*)(smem + OFF_MZ);    // [64] {mu, rstd}

    float s[8], q[8];                          // row slots: mt*2 + h
#pragma unroll
    for (int r8 = 0; r8 < 8; r8++) { s[r8] = 0.f; q[r8] = 0.f; }

#pragma unroll
    for (int mt = 0; mt < 4; mt++) {
#pragma unroll
        for (int nt = 0; nt < 8; nt++) {
            const int col = wid * 64 + nt * 8 + t4 * 2;
            const float2 bv = *(const float2*)(bias + col);
            acc[mt][nt][0] += bv.x; acc[mt][nt][1] += bv.y;
            acc[mt][nt][2] += bv.x; acc[mt][nt][3] += bv.y;
            s[mt * 2 + 0] += acc[mt][nt][0] + acc[mt][nt][1];
            q[mt * 2 + 0] += acc[mt][nt][0] * acc[mt][nt][0]
                           + acc[mt][nt][1] * acc[mt][nt][1];
            s[mt * 2 + 1] += acc[mt][nt][2] + acc[mt][nt][3];
            q[mt * 2 + 1] += acc[mt][nt][2] * acc[mt][nt][2]
                           + acc[mt][nt][3] * acc[mt][nt][3];
        }
    }
#pragma unroll
    for (int r8 = 0; r8 < 8; r8++) {
        s[r8] += __shfl_xor_sync(0xffffffffu, s[r8], 1);
        q[r8] += __shfl_xor_sync(0xffffffffu, q[r8], 1);
        s[r8] += __shfl_xor_sync(0xffffffffu, s[r8], 2);
        q[r8] += __shfl_xor_sync(0xffffffffu, q[r8], 2);
    }
    if (t4 == 0) {
#pragma unroll
        for (int r8 = 0; r8 < 8; r8++) {
            const int row = (r8 >> 1) * 16 + (r8 & 1) * 8 + g;
            ps[row * 8 + wid] = s[r8];
            pq[row * 8 + wid] = q[r8];
        }
    }
    __syncthreads();
    if (tid < 64) {
        float ss = 0.f, qq = 0.f;
#pragma unroll
        for (int w = 0; w < 8; w++) { ss += ps[tid * 8 + w]; qq += pq[tid * 8 + w]; }
        const float mu  = ss * (1.0f / 512.0f);
        const float var = qq * (1.0f / 512.0f) - mu * mu;
        mz[tid] = make_float2(mu, rsqrtf(var + 1e-5f));
    }
    __syncthreads();

#pragma unroll
    for (int mt = 0; mt < 4; mt++) {
#pragma unroll
        for (int h = 0; h < 2; h++) {
            const int row = mt * 16 + h * 8 + g;
            const float2 m = mz[row];
#pragma unroll
            for (int nt = 0; nt < 8; nt++) {
                const int col = wid * 64 + nt * 8 + t4 * 2;
                const float2 gv = *(const float2*)(gamma + col);
                const float2 tv = *(const float2*)(beta + col);
                const float v0 = acc[mt][nt][h * 2 + 0];
                const float v1 = acc[mt][nt][h * 2 + 1];
                const float o0 = fmaxf((v0 - m.x) * m.y * gv.x + tv.x, 0.0f);
                const float o1 = fmaxf((v1 - m.x) * m.y * gv.y + tv.y, 0.0f);
                *(float2*)(out + (size_t)(m0 + row) * 512 + col) = make_float2(o0, o1);
            }
        }
    }
}

extern "C" void kernel_launch(void* const* d_in, const int* in_sizes, int n_in,
                              void* d_out, int out_size)
{
    // metadata order: embeddings, W_proj, b_proj, W_enc, b_enc, ln_gamma, ln_beta
    const float* emb   = (const float*)d_in[0];
    const float* W_enc = (const float*)d_in[3];
    const float* b_enc = (const float*)d_in[4];
    const float* gam   = (const float*)d_in[5];
    const float* bet   = (const float*)d_in[6];
    float* out = (float*)d_out;

    cudaFuncSetAttribute(gemm_ln_kernel,
                         cudaFuncAttributeMaxDynamicSharedMemorySize, SMEM_TOTAL);
    gemm_ln_kernel<<<16384 / MTILE, THREADS, SMEM_TOTAL>>>(emb, W_enc, b_enc,
                                                           gam, bet, out);
}